// round 3
// baseline (speedup 1.0000x reference)
#include <cuda_runtime.h>

#define BB 16
#define NN 2048
#define KK 16
#define CC 64
#define BN (BB * NN)

#define SPLITS 4
#define SLICE (NN / SPLITS)      // 512
#define TGTB 64                  // targets per knn block
#define BUFCAP 32                // per-thread idx buffer entries

// ---------------- scratch ---------------------------------------------------
__device__ float g_A  [BN * CC];    // x @ (W_dst @ W_attn)
__device__ float g_BV [BN * 2*CC];  // interleaved: [p][4*g+{0,1}]=Bv pair, {2,3}=V pair
__device__ int   g_nbr[BN * KK];
__device__ float g_Wda[CC * CC];
__device__ float g_Wsa[CC * CC];
__device__ float g_Wpa[3 * CC];
__device__ float g_biasL[CC];

// ---------------- k0: combine weights ---------------------------------------
__global__ void combine_kernel(const float* __restrict__ W_pos,
                               const float* __restrict__ b_pos,
                               const float* __restrict__ W_attn,
                               const float* __restrict__ b_attn,
                               const float* __restrict__ W_src,
                               const float* __restrict__ W_dst) {
    int tid = threadIdx.x;
    int blk = blockIdx.x;
    if (blk < 16) {
        int r = tid >> 6, c = tid & 63;
        int k = blk * 4 + r;
        float a1 = 0.f, a2 = 0.f;
#pragma unroll 8
        for (int m = 0; m < 64; m++) {
            float w = W_attn[m * 64 + c];
            a1 = fmaf(W_dst[k * 64 + m], w, a1);
            a2 = fmaf(W_src[k * 64 + m], w, a2);
        }
        g_Wda[k * 64 + c] = a1;
        g_Wsa[k * 64 + c] = a2;
    } else {
        if (tid < 192) {
            int d = tid >> 6, c = tid & 63;
            float a = 0.f;
#pragma unroll 8
            for (int m = 0; m < 64; m++)
                a = fmaf(W_pos[d * 64 + m], W_attn[m * 64 + c], a);
            g_Wpa[tid] = a;
        } else {
            int c = tid - 192;
            float a = b_attn[c];
#pragma unroll 8
            for (int m = 0; m < 64; m++)
                a = fmaf(b_pos[m], W_attn[m * 64 + c], a);
            g_biasL[c] = a;
        }
    }
}

// ---------------- k1: per-point GEMMs, one matrix per blockIdx.y -------------
__global__ void feat_gemm_kernel(const float* __restrict__ x,
                                 const float* __restrict__ W_val) {
    __shared__ float xs[64][68];
    __shared__ float ws[64 * 64];
    int tid = threadIdx.x;
    int p0 = blockIdx.x * 64;
    int m = blockIdx.y;
    const float* src = (m == 0) ? g_Wda : (m == 1) ? g_Wsa : W_val;

    for (int idx = tid; idx < 4096; idx += 256) {
        int p = idx >> 6, k = idx & 63;
        xs[k][p] = x[(p0 + p) * 64 + k];
        ws[idx] = src[idx];
    }
    __syncthreads();

    int tx = tid & 15, ty = tid >> 4;
    float acc[4][4];
#pragma unroll
    for (int i = 0; i < 4; i++)
#pragma unroll
        for (int j = 0; j < 4; j++) acc[i][j] = 0.f;

#pragma unroll 8
    for (int k = 0; k < 64; k++) {
        float4 xv = *(const float4*)&xs[k][ty * 4];
        float4 wv = *(const float4*)&ws[k * 64 + tx * 4];
        acc[0][0] = fmaf(xv.x, wv.x, acc[0][0]);
        acc[0][1] = fmaf(xv.x, wv.y, acc[0][1]);
        acc[0][2] = fmaf(xv.x, wv.z, acc[0][2]);
        acc[0][3] = fmaf(xv.x, wv.w, acc[0][3]);
        acc[1][0] = fmaf(xv.y, wv.x, acc[1][0]);
        acc[1][1] = fmaf(xv.y, wv.y, acc[1][1]);
        acc[1][2] = fmaf(xv.y, wv.z, acc[1][2]);
        acc[1][3] = fmaf(xv.y, wv.w, acc[1][3]);
        acc[2][0] = fmaf(xv.z, wv.x, acc[2][0]);
        acc[2][1] = fmaf(xv.z, wv.y, acc[2][1]);
        acc[2][2] = fmaf(xv.z, wv.z, acc[2][2]);
        acc[2][3] = fmaf(xv.z, wv.w, acc[2][3]);
        acc[3][0] = fmaf(xv.w, wv.x, acc[3][0]);
        acc[3][1] = fmaf(xv.w, wv.y, acc[3][1]);
        acc[3][2] = fmaf(xv.w, wv.z, acc[3][2]);
        acc[3][3] = fmaf(xv.w, wv.w, acc[3][3]);
    }

    int c0 = tx * 4;
#pragma unroll
    for (int i = 0; i < 4; i++) {
        int p = p0 + ty * 4 + i;
        if (m == 0) {
            *(float4*)&g_A[(size_t)p * 64 + c0] =
                make_float4(acc[i][0], acc[i][1], acc[i][2], acc[i][3]);
        } else if (m == 1) {
            *(float2*)&g_BV[(size_t)p * 128 + c0 * 2]     = make_float2(acc[i][0], acc[i][1]);
            *(float2*)&g_BV[(size_t)p * 128 + c0 * 2 + 4] = make_float2(acc[i][2], acc[i][3]);
        } else {
            *(float2*)&g_BV[(size_t)p * 128 + c0 * 2 + 2] = make_float2(acc[i][0], acc[i][1]);
            *(float2*)&g_BV[(size_t)p * 128 + c0 * 2 + 6] = make_float2(acc[i][2], acc[i][3]);
        }
    }
}

// ---------------- k2: KNN — 4-way candidate split + smem merge --------------
__device__ __forceinline__ void insert16(float (&bd)[KK], int (&bi)[KK],
                                         float d, int id) {
#pragma unroll
    for (int s = 0; s < KK; s++) {
        bool p = d < bd[s];
        float nbd = p ? d : bd[s];
        float nd  = p ? bd[s] : d;
        int   nbi = p ? id : bi[s];
        int   nid = p ? bi[s] : id;
        bd[s] = nbd; d = nd; bi[s] = nbi; id = nid;
    }
}

__global__ void __launch_bounds__(256) knn_kernel(const float* __restrict__ pos) {
    extern __shared__ char ksm[];
    float4* spos = (float4*)ksm;                  // 32 KB
    int*    sbuf = (int*)(ksm + NN * 16);         // 32 KB idx buffer / merge lists

    int tid = threadIdx.x;
    int lt  = tid & 63;        // local target
    int sp  = tid >> 6;        // split 0..3
    int base = blockIdx.y * NN;
    int ilc  = blockIdx.x * TGTB + lt;   // target index within cloud

    for (int idx = tid; idx < NN; idx += 256) {
        const float* p = pos + (size_t)(base + idx) * 3;
        spos[idx] = make_float4(p[0], p[1], p[2], 0.f);
    }
    __syncthreads();

    float4 pi = spos[ilc];
    int j0 = sp * SLICE;

    float bd[KK];
    int bi[KK];
    // init: first 16 slice candidates, self -> +inf
#pragma unroll
    for (int t = 0; t < KK; t++) {
        int j = j0 + t;
        float4 pj = spos[j];
        float dx = pi.x - pj.x, dy = pi.y - pj.y, dz = pi.z - pj.z;
        float d2 = fmaf(dx, dx, fmaf(dy, dy, dz * dz));
        bd[t] = (j == ilc) ? 3.4e38f : d2;
        bi[t] = j;
    }
    // bitonic sort 16 (ascending)
#pragma unroll
    for (int k = 2; k <= 16; k <<= 1)
#pragma unroll
        for (int jj = k >> 1; jj > 0; jj >>= 1)
#pragma unroll
            for (int i = 0; i < 16; i++) {
                int l = i ^ jj;
                if (l > i) {
                    bool up = ((i & k) == 0);
                    bool sw = up ? (bd[i] > bd[l]) : (bd[i] < bd[l]);
                    float tv = sw ? bd[l] : bd[i];
                    float tw = sw ? bd[i] : bd[l];
                    int   ui = sw ? bi[l] : bi[i];
                    int   uj = sw ? bi[i] : bi[l];
                    bd[i] = tv; bd[l] = tw; bi[i] = ui; bi[l] = uj;
                }
            }

    const int bounds[5] = {16, 48, 112, 240, 512};
    int cnt = 0;
#pragma unroll
    for (int ch = 0; ch < 4; ch++) {
        int lo = j0 + bounds[ch], hi = j0 + bounds[ch + 1];
#pragma unroll 4
        for (int j = lo; j < hi; j++) {
            float4 pj = spos[j];
            float dx = pi.x - pj.x, dy = pi.y - pj.y, dz = pi.z - pj.z;
            float d2 = fmaf(dx, dx, fmaf(dy, dy, dz * dz));
            if (d2 < bd[KK - 1] && j != ilc) {
                if (cnt < BUFCAP) {
                    sbuf[cnt * 256 + tid] = j;
                    cnt++;
                } else {
                    insert16(bd, bi, d2, j);
                }
            }
        }
        unsigned wmax = __reduce_max_sync(0xffffffffu, (unsigned)cnt);
        for (unsigned m = 0; m < wmax; m++) {
            if ((int)m < cnt) {
                int j = sbuf[m * 256 + tid];
                float4 pj = spos[j];
                float dx = pi.x - pj.x, dy = pi.y - pj.y, dz = pi.z - pj.z;
                float d2 = fmaf(dx, dx, fmaf(dy, dy, dz * dz));
                if (d2 < bd[KK - 1]) insert16(bd, bi, d2, j);
            }
        }
        cnt = 0;
    }

    // merge: write slice lists to smem, split-0 threads merge 4 lists
    __syncthreads();
    uint2* lists = (uint2*)sbuf;   // 256 * 16 * 8B = 32 KB
#pragma unroll
    for (int k = 0; k < KK; k++)
        lists[tid * KK + k] = make_uint2(__float_as_uint(bd[k]), (unsigned)bi[k]);
    __syncthreads();

    if (tid < TGTB) {
#pragma unroll
        for (int src = 1; src < SPLITS; src++) {
#pragma unroll
            for (int k = 0; k < KK; k++) {
                uint2 e = lists[(tid + 64 * src) * KK + k];
                float d2 = __uint_as_float(e.x);
                if (d2 < bd[KK - 1]) insert16(bd, bi, d2, (int)e.y);
            }
        }
#pragma unroll
        for (int k = 0; k < KK; k++)
            g_nbr[(size_t)(base + ilc) * KK + k] = base + bi[k];
    }
}

// ---------------- k3: edge kernel -------------------------------------------
__global__ void edge_kernel(const float* __restrict__ pos,
                            const float* __restrict__ W_pos,
                            const float* __restrict__ b_pos,
                            float* __restrict__ out) {
    int tid = threadIdx.x;
    int lane = tid & 31;
    int warp = tid >> 5;
    int i = blockIdx.x * 8 + warp;
    int c0 = lane * 2;

    float2 Wpa0 = *(const float2*)&g_Wpa[0 * 64 + c0];
    float2 Wpa1 = *(const float2*)&g_Wpa[1 * 64 + c0];
    float2 Wpa2 = *(const float2*)&g_Wpa[2 * 64 + c0];
    float2 Wp0  = *(const float2*)&W_pos[0 * 64 + c0];
    float2 Wp1  = *(const float2*)&W_pos[1 * 64 + c0];
    float2 Wp2  = *(const float2*)&W_pos[2 * 64 + c0];
    float2 bp   = *(const float2*)&b_pos[c0];
    float2 bL   = *(const float2*)&g_biasL[c0];
    float2 Ai   = *(const float2*)&g_A[(size_t)i * 64 + c0];
    float basex = Ai.x + bL.x;
    float basey = Ai.y + bL.y;

    float pix = pos[i * 3 + 0];
    float piy = pos[i * 3 + 1];
    float piz = pos[i * 3 + 2];

    int myn = (lane < KK) ? g_nbr[(size_t)i * KK + lane] : i;
    float mpx = pos[myn * 3 + 0];
    float mpy = pos[myn * 3 + 1];
    float mpz = pos[myn * 3 + 2];

    float sx = 0.f, sy = 0.f, ox = 0.f, oy = 0.f;

#pragma unroll 4
    for (int j = 0; j <= KK; j++) {
        int jj  = __shfl_sync(0xffffffffu, myn, j);
        float pjx = __shfl_sync(0xffffffffu, mpx, j);
        float pjy = __shfl_sync(0xffffffffu, mpy, j);
        float pjz = __shfl_sync(0xffffffffu, mpz, j);
        float dx = pix - pjx, dy = piy - pjy, dz = piz - pjz;

        float4 bv = *(const float4*)&g_BV[(size_t)jj * 128 + lane * 4];

        float lgx = basex - bv.x + dx * Wpa0.x + dy * Wpa1.x + dz * Wpa2.x;
        float lgy = basey - bv.y + dx * Wpa0.y + dy * Wpa1.y + dz * Wpa2.y;
        float px = __expf(lgx);
        float py = __expf(lgy);

        float dvx = dx * Wp0.x + dy * Wp1.x + dz * Wp2.x + bp.x;
        float dvy = dx * Wp0.y + dy * Wp1.y + dz * Wp2.y + bp.y;

        sx += px;
        sy += py;
        ox = fmaf(px, bv.z + dvx, ox);
        oy = fmaf(py, bv.w + dvy, oy);
    }

    float2 r;
    r.x = ox / sx;
    r.y = oy / sy;
    *(float2*)&out[(size_t)i * 64 + c0] = r;
}

// ---------------- launch -----------------------------------------------------
extern "C" void kernel_launch(void* const* d_in, const int* in_sizes, int n_in,
                              void* d_out, int out_size) {
    const float* x      = (const float*)d_in[0];
    const float* pos    = (const float*)d_in[1];
    const float* W_pos  = (const float*)d_in[3];
    const float* b_pos  = (const float*)d_in[4];
    const float* W_attn = (const float*)d_in[5];
    const float* b_attn = (const float*)d_in[6];
    const float* W_val  = (const float*)d_in[7];
    const float* W_src  = (const float*)d_in[8];
    const float* W_dst  = (const float*)d_in[9];
    float* out = (float*)d_out;

    const int knn_smem = NN * 16 + 256 * BUFCAP * 4;  // 64 KB
    cudaFuncSetAttribute(knn_kernel, cudaFuncAttributeMaxDynamicSharedMemorySize,
                         knn_smem);

    combine_kernel<<<17, 256>>>(W_pos, b_pos, W_attn, b_attn, W_src, W_dst);
    feat_gemm_kernel<<<dim3(BN / 64, 3), 256>>>(x, W_val);
    knn_kernel<<<dim3(NN / TGTB, BB), 256, knn_smem>>>(pos);
    edge_kernel<<<BN / 8, 256>>>(pos, W_pos, b_pos, out);
}